// round 2
// baseline (speedup 1.0000x reference)
#include <cuda_runtime.h>
#include <math.h>

#define Lc   6
#define Bc   32
#define Tc   256
#define SAc  512
#define STc  128
#define Dc   1024
#define Hc   16
#define HDc  64
#define DFFc 4096
#define OUTc 3

// ---------------- scratch (static device globals; no allocation) ----------------
__device__ float g_x [Bc*Tc*Dc];
__device__ float g_h [Bc*Tc*Dc];
__device__ float g_q [Bc*Tc*Dc];
__device__ float g_ks[Bc*Tc*Dc];
__device__ float g_vs[Bc*Tc*Dc];
__device__ float g_ka[Bc*SAc*Dc];
__device__ float g_va[Bc*SAc*Dc];
__device__ float g_kt[Bc*STc*Dc];
__device__ float g_vt[Bc*STc*Dc];
__device__ float g_o [Bc*Tc*Dc];
__device__ float g_ff[Bc*Tc*DFFc];
__device__ float g_ada[Bc*6*Dc];
__device__ float g_sc[Bc*Dc];

// ---------------- small helpers ----------------
__device__ __forceinline__ float block_reduce_sum(float v, float* red) {
    int tid = threadIdx.x;
    red[tid] = v;
    __syncthreads();
    #pragma unroll
    for (int s = 128; s > 0; s >>= 1) {
        if (tid < s) red[tid] += red[tid + s];
        __syncthreads();
    }
    float r = red[0];
    __syncthreads();
    return r;
}

// ---------------- elementwise kernels ----------------
__global__ void copy_kernel(const float* __restrict__ src, float* __restrict__ dst, int n) {
    int i = blockIdx.x * blockDim.x + threadIdx.x;
    if (i < n) dst[i] = src[i];
}

__global__ void silu_kernel(const float* __restrict__ c, float* __restrict__ out, int n) {
    int i = blockIdx.x * blockDim.x + threadIdx.x;
    if (i < n) {
        float x = c[i];
        out[i] = x / (1.f + expf(-x));
    }
}

// h = ln(x) * (1 + ada[:, off_scale + d]) + ada[:, off_shift + d]
__global__ void ln_mod_kernel(const float* __restrict__ x, const float* __restrict__ ada,
                              int off_shift, int off_scale, float* __restrict__ out) {
    __shared__ float red[256];
    int row = blockIdx.x;              // b*T + t
    int b   = row / Tc;
    int tid = threadIdx.x;
    const float* xr = x + row * Dc;

    float v[4];
    float s = 0.f;
    #pragma unroll
    for (int i = 0; i < 4; i++) { v[i] = xr[tid + i*256]; s += v[i]; }
    float mean = block_reduce_sum(s, red) * (1.f / (float)Dc);

    float sq = 0.f;
    #pragma unroll
    for (int i = 0; i < 4; i++) { float d = v[i] - mean; sq += d * d; }
    float var = block_reduce_sum(sq, red) * (1.f / (float)Dc);
    float rstd = rsqrtf(var + 1e-5f);

    const float* ab = ada + b * (6 * Dc);
    #pragma unroll
    for (int i = 0; i < 4; i++) {
        int d = tid + i*256;
        float a = (v[i] - mean) * rstd;
        out[row * Dc + d] = a * (1.f + ab[off_scale + d]) + ab[off_shift + d];
    }
}

// in-place RMSNorm (per head, HD=64) + RoPE + optional uniform multiplier
// one warp per (b, s, h) row; lane handles dims {l, l+32} (the rotate_half pair)
__global__ void rmsrope_kernel(float* __restrict__ t, const float* __restrict__ w,
                               int S, float cmul, const float* __restrict__ gate) {
    int warp = (blockIdx.x * blockDim.x + threadIdx.x) >> 5;
    int lane = threadIdx.x & 31;
    int row  = warp;                   // in [0, B*S*H)
    int s    = (row / Hc) % S;
    float* p = t + row * HDc;

    float x0 = p[lane];
    float x1 = p[lane + 32];
    float ss = x0*x0 + x1*x1;
    #pragma unroll
    for (int o = 16; o; o >>= 1) ss += __shfl_xor_sync(0xffffffffu, ss, o);
    float inv = rsqrtf(ss * (1.f / (float)HDc) + 1e-6f);
    x0 = x0 * inv * w[lane];
    x1 = x1 * inv * w[lane + 32];

    // inv_freq[l] = 10000^(-2l/64) = exp(-l * ln(10000)/32)
    float fr = (float)s * expf(-(float)lane * 0.28782313662425575f);
    float c  = cosf(fr);
    float sn = sinf(fr);

    float mult = cmul;
    if (gate) mult *= 1.f / (1.f + expf(-gate[0]));

    p[lane]      = (x0 * c - x1 * sn) * mult;   // d < 32: rot = -x[d+32]
    p[lane + 32] = (x1 * c + x0 * sn) * mult;   // d >= 32: rot = x[d-32]
}

// small GEMM for ada: C[b,n] = A[b,:] @ W[:,n] + bias[n]   (M=32 rows)
__global__ void small_gemm_kernel(const float* __restrict__ A, const float* __restrict__ W,
                                  const float* __restrict__ bias, float* __restrict__ C,
                                  int Nn, int Kk) {
    int n = blockIdx.x * blockDim.x + threadIdx.x;
    int b = blockIdx.y;
    if (n >= Nn) return;
    const float* a = A + b * Kk;
    float acc = 0.f;
    #pragma unroll 4
    for (int k = 0; k < Kk; k++) acc += a[k] * W[k * Nn + n];
    C[b * Nn + n] = acc + (bias ? bias[n] : 0.f);
}

// ---------------- main SGEMM: 128x128 tile, K-tile 16, 256 threads, 8x8/thread ----------------
// EPI 0: C = acc + bias
// EPI 1: C = gelu(acc + bias)          (tanh approximation)
// EPI 2: X[row, col] += gmod[row/T * gstride + col] * (acc + bias)
template <int EPI>
__global__ __launch_bounds__(256) void sgemm(
    const float* __restrict__ A, const float* __restrict__ W,
    const float* __restrict__ bias, float* __restrict__ C,
    int M, int N, int K,
    const float* __restrict__ gmod, int gstride, float* __restrict__ X)
{
    __shared__ float As[16][128];
    __shared__ float Bs[16][128];

    int tid  = threadIdx.x;
    int row0 = blockIdx.y * 128;
    int col0 = blockIdx.x * 128;

    int am = tid >> 1;             // 0..127
    int ak = (tid & 1) * 8;        // 0 or 8
    int bk = tid >> 4;             // 0..15
    int bn = (tid & 15) * 8;       // 0..120

    int ty = tid >> 4;             // 0..15
    int tx = tid & 15;             // 0..15

    float acc[8][8];
    #pragma unroll
    for (int i = 0; i < 8; i++)
        #pragma unroll
        for (int j = 0; j < 8; j++) acc[i][j] = 0.f;

    for (int k0 = 0; k0 < K; k0 += 16) {
        // load A tile (128 x 16)
        float4 a0 = *(const float4*)&A[(row0 + am) * K + k0 + ak];
        float4 a1 = *(const float4*)&A[(row0 + am) * K + k0 + ak + 4];
        As[ak+0][am] = a0.x; As[ak+1][am] = a0.y; As[ak+2][am] = a0.z; As[ak+3][am] = a0.w;
        As[ak+4][am] = a1.x; As[ak+5][am] = a1.y; As[ak+6][am] = a1.z; As[ak+7][am] = a1.w;
        // load B tile (16 x 128)
        float4 b0 = *(const float4*)&W[(k0 + bk) * N + col0 + bn];
        float4 b1 = *(const float4*)&W[(k0 + bk) * N + col0 + bn + 4];
        *(float4*)&Bs[bk][bn]     = b0;
        *(float4*)&Bs[bk][bn + 4] = b1;
        __syncthreads();

        #pragma unroll
        for (int k = 0; k < 16; k++) {
            float a[8], b[8];
            #pragma unroll
            for (int i = 0; i < 8; i++) a[i] = As[k][ty*8 + i];
            #pragma unroll
            for (int j = 0; j < 8; j++) b[j] = Bs[k][tx*8 + j];
            #pragma unroll
            for (int i = 0; i < 8; i++)
                #pragma unroll
                for (int j = 0; j < 8; j++)
                    acc[i][j] = fmaf(a[i], b[j], acc[i][j]);
        }
        __syncthreads();
    }

    #pragma unroll
    for (int i = 0; i < 8; i++) {
        int row = row0 + ty*8 + i;
        #pragma unroll
        for (int j = 0; j < 8; j++) {
            int col = col0 + tx*8 + j;
            float c = acc[i][j] + (bias ? bias[col] : 0.f);
            if (EPI == 0) {
                C[row * N + col] = c;
            } else if (EPI == 1) {
                float t = 0.7978845608028654f * (c + 0.044715f * c * c * c);
                C[row * N + col] = 0.5f * c * (1.f + tanhf(t));
            } else {
                int b = row / Tc;
                X[row * N + col] += gmod[b * gstride + col] * c;
            }
        }
    }
}

// ---------------- flash attention over 3 KV segments ----------------
// grid: (T/128, B*H); 128 threads; 1 query/thread, q & o accumulator in registers.
// q pre-scaled by 1/sqrt(HD); k_task pre-scaled by sigmoid(gate).
__global__ __launch_bounds__(128) void flash_kernel(
    const float* __restrict__ q,
    const float* __restrict__ ks, const float* __restrict__ vs,
    const float* __restrict__ ka, const float* __restrict__ va,
    const float* __restrict__ kt, const float* __restrict__ vt,
    float* __restrict__ o)
{
    __shared__ float4 Ks4[32][16];
    __shared__ float4 Vs4[32][16];

    int tid = threadIdx.x;
    int bh  = blockIdx.y;
    int b   = bh / Hc, h = bh % Hc;
    int qi  = blockIdx.x * 128 + tid;

    float qr[64], oa[64];
    const float* qp = q + (b*Tc + qi) * Dc + h * HDc;
    #pragma unroll
    for (int j = 0; j < 16; j++) {
        float4 v4 = *(const float4*)&qp[j*4];
        qr[4*j] = v4.x; qr[4*j+1] = v4.y; qr[4*j+2] = v4.z; qr[4*j+3] = v4.w;
    }
    #pragma unroll
    for (int d = 0; d < 64; d++) oa[d] = 0.f;
    float m = -1e30f, l = 0.f;

    const float* Kseg[3] = {ks, ka, kt};
    const float* Vseg[3] = {vs, va, vt};
    const int    Slen[3] = {Tc, SAc, STc};

    #pragma unroll
    for (int seg = 0; seg < 3; seg++) {
        const float* K = Kseg[seg];
        const float* V = Vseg[seg];
        int S = Slen[seg];
        for (int s0 = 0; s0 < S; s0 += 32) {
            __syncthreads();
            #pragma unroll
            for (int i = 0; i < 4; i++) {
                int idx = tid + i*128;          // 0..511
                int r = idx >> 4, cc = idx & 15;
                int base = (b*S + s0 + r) * Dc + h * HDc + cc*4;
                Ks4[r][cc] = *(const float4*)&K[base];
                Vs4[r][cc] = *(const float4*)&V[base];
            }
            __syncthreads();

            float sc[32];
            float tmax = -1e30f;
            #pragma unroll
            for (int s = 0; s < 32; s++) {
                float d0 = 0.f, d1 = 0.f, d2 = 0.f, d3 = 0.f;
                #pragma unroll
                for (int j = 0; j < 16; j++) {
                    float4 kv = Ks4[s][j];
                    d0 = fmaf(qr[4*j],   kv.x, d0);
                    d1 = fmaf(qr[4*j+1], kv.y, d1);
                    d2 = fmaf(qr[4*j+2], kv.z, d2);
                    d3 = fmaf(qr[4*j+3], kv.w, d3);
                }
                float d = (d0 + d1) + (d2 + d3);
                sc[s] = d;
                tmax = fmaxf(tmax, d);
            }
            float mnew = fmaxf(m, tmax);
            float corr = __expf(m - mnew);
            l *= corr;
            #pragma unroll
            for (int d = 0; d < 64; d++) oa[d] *= corr;
            #pragma unroll
            for (int s = 0; s < 32; s++) {
                float p = __expf(sc[s] - mnew);
                l += p;
                #pragma unroll
                for (int j = 0; j < 16; j++) {
                    float4 vv = Vs4[s][j];
                    oa[4*j]   = fmaf(p, vv.x, oa[4*j]);
                    oa[4*j+1] = fmaf(p, vv.y, oa[4*j+1]);
                    oa[4*j+2] = fmaf(p, vv.z, oa[4*j+2]);
                    oa[4*j+3] = fmaf(p, vv.w, oa[4*j+3]);
                }
            }
            m = mnew;
        }
    }

    float invl = 1.f / l;
    float* op = o + (b*Tc + qi) * Dc + h * HDc;
    #pragma unroll
    for (int j = 0; j < 16; j++) {
        float4 v4 = make_float4(oa[4*j]*invl, oa[4*j+1]*invl, oa[4*j+2]*invl, oa[4*j+3]*invl);
        *(float4*)&op[j*4] = v4;
    }
}

// ---------------- final LN + tiny projection ----------------
__global__ void final_kernel(const float* __restrict__ x, const float* __restrict__ lw,
                             const float* __restrict__ lb, const float* __restrict__ Wout,
                             const float* __restrict__ bout, float* __restrict__ out) {
    __shared__ float red[256];
    int row = blockIdx.x;
    int tid = threadIdx.x;
    const float* xr = x + row * Dc;

    float v[4];
    float s = 0.f;
    #pragma unroll
    for (int i = 0; i < 4; i++) { v[i] = xr[tid + i*256]; s += v[i]; }
    float mean = block_reduce_sum(s, red) * (1.f / (float)Dc);
    float sq = 0.f;
    #pragma unroll
    for (int i = 0; i < 4; i++) { float d = v[i] - mean; sq += d * d; }
    float var = block_reduce_sum(sq, red) * (1.f / (float)Dc);
    float rstd = rsqrtf(var + 1e-5f);

    float p0 = 0.f, p1 = 0.f, p2 = 0.f;
    #pragma unroll
    for (int i = 0; i < 4; i++) {
        int d = tid + i*256;
        float y = (v[i] - mean) * rstd * lw[d] + lb[d];
        p0 = fmaf(y, Wout[d*OUTc + 0], p0);
        p1 = fmaf(y, Wout[d*OUTc + 1], p1);
        p2 = fmaf(y, Wout[d*OUTc + 2], p2);
    }
    p0 = block_reduce_sum(p0, red);
    p1 = block_reduce_sum(p1, red);
    p2 = block_reduce_sum(p2, red);
    if (tid == 0) {
        out[row*OUTc + 0] = p0 + bout[0];
        out[row*OUTc + 1] = p1 + bout[1];
        out[row*OUTc + 2] = p2 + bout[2];
    }
}

// ---------------- launch ----------------
extern "C" void kernel_launch(void* const* d_in, const int* in_sizes, int n_in,
                              void* d_out, int out_size)
{
    (void)in_sizes; (void)n_in; (void)out_size;
    const float* x    = (const float*)d_in[0];
    const float* cond = (const float*)d_in[1];
    const float* adp  = (const float*)d_in[2];
    const float* task = (const float*)d_in[3];
    const float* Wq   = (const float*)d_in[4];
    const float* bq   = (const float*)d_in[5];
    const float* Wks  = (const float*)d_in[6];
    const float* Wvs  = (const float*)d_in[7];
    const float* Wka  = (const float*)d_in[8];
    const float* Wva  = (const float*)d_in[9];
    const float* Wkt  = (const float*)d_in[10];
    const float* Wvt  = (const float*)d_in[11];
    const float* Wo   = (const float*)d_in[12];
    const float* bo   = (const float*)d_in[13];
    const float* qnw  = (const float*)d_in[14];
    const float* knw  = (const float*)d_in[15];
    const float* gate = (const float*)d_in[16];
    const float* Wada = (const float*)d_in[17];
    const float* bada = (const float*)d_in[18];
    const float* W1   = (const float*)d_in[19];
    const float* b1   = (const float*)d_in[20];
    const float* W2   = (const float*)d_in[21];
    const float* b2   = (const float*)d_in[22];
    const float* lnfw = (const float*)d_in[23];
    const float* lnfb = (const float*)d_in[24];
    const float* Wout = (const float*)d_in[25];
    const float* bout = (const float*)d_in[26];
    float* out = (float*)d_out;

    float *px, *ph, *pq, *pks, *pvs, *pka, *pva, *pkt, *pvt, *po, *pff, *pada, *psc;
    cudaGetSymbolAddress((void**)&px,  g_x);
    cudaGetSymbolAddress((void**)&ph,  g_h);
    cudaGetSymbolAddress((void**)&pq,  g_q);
    cudaGetSymbolAddress((void**)&pks, g_ks);
    cudaGetSymbolAddress((void**)&pvs, g_vs);
    cudaGetSymbolAddress((void**)&pka, g_ka);
    cudaGetSymbolAddress((void**)&pva, g_va);
    cudaGetSymbolAddress((void**)&pkt, g_kt);
    cudaGetSymbolAddress((void**)&pvt, g_vt);
    cudaGetSymbolAddress((void**)&po,  g_o);
    cudaGetSymbolAddress((void**)&pff, g_ff);
    cudaGetSymbolAddress((void**)&pada, g_ada);
    cudaGetSymbolAddress((void**)&psc,  g_sc);

    copy_kernel<<<(Bc*Tc*Dc)/256, 256>>>(x, px, Bc*Tc*Dc);
    silu_kernel<<<(Bc*Dc)/256, 256>>>(cond, psc, Bc*Dc);

    const int MT  = Bc*Tc;     // 8192
    const int MA  = Bc*SAc;    // 16384
    const int MST = Bc*STc;    // 4096

    for (int i = 0; i < Lc; i++) {
        const size_t dd  = (size_t)Dc*Dc;
        small_gemm_kernel<<<dim3((6*Dc)/256, Bc), 256>>>(
            psc, Wada + (size_t)i*Dc*6*Dc, bada + (size_t)i*6*Dc, pada, 6*Dc, Dc);

        ln_mod_kernel<<<MT, 256>>>(px, pada, 0, Dc, ph);

        sgemm<0><<<dim3(Dc/128, MT/128), 256>>>(ph, Wq  + i*dd, bq + (size_t)i*Dc, pq,  MT, Dc, Dc, nullptr, 0, nullptr);
        sgemm<0><<<dim3(Dc/128, MT/128), 256>>>(ph, Wks + i*dd, nullptr,           pks, MT, Dc, Dc, nullptr, 0, nullptr);
        sgemm<0><<<dim3(Dc/128, MT/128), 256>>>(ph, Wvs + i*dd, nullptr,           pvs, MT, Dc, Dc, nullptr, 0, nullptr);
        sgemm<0><<<dim3(Dc/128, MA/128), 256>>>(adp, Wka + i*dd, nullptr,          pka, MA, Dc, Dc, nullptr, 0, nullptr);
        sgemm<0><<<dim3(Dc/128, MA/128), 256>>>(adp, Wva + i*dd, nullptr,          pva, MA, Dc, Dc, nullptr, 0, nullptr);
        sgemm<0><<<dim3(Dc/128, MST/128), 256>>>(task, Wkt + i*dd, nullptr,        pkt, MST, Dc, Dc, nullptr, 0, nullptr);
        sgemm<0><<<dim3(Dc/128, MST/128), 256>>>(task, Wvt + i*dd, nullptr,        pvt, MST, Dc, Dc, nullptr, 0, nullptr);

        // q: rms(qnw) + rope + fold 1/sqrt(HD); keys: rms(knw) + rope; k_task also * sigmoid(gate)
        rmsrope_kernel<<<(Bc*Tc*Hc*32)/256,  256>>>(pq,  qnw + (size_t)i*HDc, Tc,  0.125f, nullptr);
        rmsrope_kernel<<<(Bc*Tc*Hc*32)/256,  256>>>(pks, knw + (size_t)i*HDc, Tc,  1.f,    nullptr);
        rmsrope_kernel<<<(Bc*SAc*Hc*32)/256, 256>>>(pka, knw + (size_t)i*HDc, SAc, 1.f,    nullptr);
        rmsrope_kernel<<<(Bc*STc*Hc*32)/256, 256>>>(pkt, knw + (size_t)i*HDc, STc, 1.f,    gate + i);

        flash_kernel<<<dim3(Tc/128, Bc*Hc), 128>>>(pq, pks, pvs, pka, pva, pkt, pvt, po);

        // x += g1 * (o @ Wo + bo)
        sgemm<2><<<dim3(Dc/128, MT/128), 256>>>(po, Wo + i*dd, bo + (size_t)i*Dc, nullptr,
                                                MT, Dc, Dc, pada + 2*Dc, 6*Dc, px);

        ln_mod_kernel<<<MT, 256>>>(px, pada, 3*Dc, 4*Dc, ph);

        // ff = gelu(h2 @ W1 + b1)
        sgemm<1><<<dim3(DFFc/128, MT/128), 256>>>(ph, W1 + (size_t)i*Dc*DFFc, b1 + (size_t)i*DFFc, pff,
                                                  MT, DFFc, Dc, nullptr, 0, nullptr);
        // x += g2 * (ff @ W2 + b2)
        sgemm<2><<<dim3(Dc/128, MT/128), 256>>>(pff, W2 + (size_t)i*DFFc*Dc, b2 + (size_t)i*Dc, nullptr,
                                                MT, Dc, DFFc, pada + 5*Dc, 6*Dc, px);
    }

    final_kernel<<<MT, 256>>>(px, lnfw, lnfb, Wout, bout, out);
}

// round 4
// speedup vs baseline: 1.8942x; 1.8942x over previous
#include <cuda_runtime.h>
#include <cuda_bf16.h>
#include <math.h>
#include <stdint.h>

#define Lc   6
#define Bc   32
#define Tc   256
#define SAc  512
#define STc  128
#define Dc   1024
#define Hc   16
#define HDc  64
#define DFFc 4096
#define OUTc 3
#define MTc  (Bc*Tc)     // 8192
#define MAc  (Bc*SAc)    // 16384
#define MSc  (Bc*STc)    // 4096
#define DDc  (Dc*Dc)
#define WPLc (8*DDc + Dc*DFFc + DFFc*Dc)   // bf16 elems per layer

// ---------------- scratch (static device globals; no allocation) ----------------
__device__ float g_x [MTc*Dc];
__device__ float g_q [MTc*Dc];
__device__ float g_ks[MTc*Dc];
__device__ float g_vs[MTc*Dc];
__device__ float g_ka[MAc*Dc];
__device__ float g_va[MAc*Dc];
__device__ float g_kt[MSc*Dc];
__device__ float g_vt[MSc*Dc];
__device__ float g_ada[Bc*6*Dc];
__device__ float g_sc[Bc*Dc];

__device__ __nv_bfloat16 g_h_hi[MTc*Dc],  g_h_lo[MTc*Dc];
__device__ __nv_bfloat16 g_o_hi[MTc*Dc],  g_o_lo[MTc*Dc];
__device__ __nv_bfloat16 g_ff_hi[MTc*DFFc], g_ff_lo[MTc*DFFc];
__device__ __nv_bfloat16 g_adp_hi[MAc*Dc], g_adp_lo[MAc*Dc];
__device__ __nv_bfloat16 g_tsk_hi[MSc*Dc], g_tsk_lo[MSc*Dc];
__device__ __nv_bfloat16 g_w_hi[Lc*WPLc], g_w_lo[Lc*WPLc];

// ---------------- PTX helpers (arch-neutral: mma.sync + cp.async) ----------------
__device__ __forceinline__ uint32_t smem_u32(const void* p) {
    uint32_t a;
    asm("{ .reg .u64 t; cvta.to.shared.u64 t, %1; cvt.u32.u64 %0, t; }" : "=r"(a) : "l"(p));
    return a;
}

__device__ __forceinline__ void mma_bf16(float* c, const uint32_t* a, const uint32_t* b) {
    asm volatile(
        "mma.sync.aligned.m16n8k16.row.col.f32.bf16.bf16.f32 "
        "{%0,%1,%2,%3}, {%4,%5,%6,%7}, {%8,%9}, {%0,%1,%2,%3};"
        : "+f"(c[0]), "+f"(c[1]), "+f"(c[2]), "+f"(c[3])
        : "r"(a[0]), "r"(a[1]), "r"(a[2]), "r"(a[3]), "r"(b[0]), "r"(b[1]));
}

__device__ __forceinline__ void cpa16(uint32_t d, const void* s) {
    asm volatile("cp.async.cg.shared.global [%0], [%1], 16;" :: "r"(d), "l"(s));
}
#define CP_COMMIT() asm volatile("cp.async.commit_group;" ::: "memory")

__device__ __forceinline__ float gelu_t(float c) {
    float t = 0.7978845608028654f * (c + 0.044715f * c * c * c);
    return 0.5f * c * (1.f + tanhf(t));
}

// ---------------- bf16 3-pass warp-MMA GEMM ----------------
// D[M,N] = A[M,K] @ Wt[N,K]^T, fp32 accum; A=Ahi+Alo, B=Bhi+Blo; 3 passes.
// Block tile 128x128, 8 warps (2m x 4n), warp tile 64x32, K-tile 32.
// Smem per stage: Ahi|Alo|Bhi|Blo, each 128 rows x 80B (32 bf16 padded). 2 stages.
// EPI 0: C = acc + bias (f32)
// EPI 1: gelu(acc + bias) -> Chi/Clo bf16 split
// EPI 2: X += gmod[row/Tc, col] * (acc + bias)
#define STG   40960
#define GSMEM (2*STG)
template <int EPI>
__global__ __launch_bounds__(256) void mma_gemm(
    const __nv_bfloat16* __restrict__ Ahi, const __nv_bfloat16* __restrict__ Alo,
    const __nv_bfloat16* __restrict__ Bhi, const __nv_bfloat16* __restrict__ Blo,
    const float* __restrict__ bias, float* __restrict__ C,
    int M, int N, int K,
    const float* __restrict__ gmod, int gstride, float* __restrict__ X,
    __nv_bfloat16* __restrict__ Chi, __nv_bfloat16* __restrict__ Clo)
{
    extern __shared__ __align__(16) char smem[];
    const int tid  = threadIdx.x;
    const int row0 = blockIdx.y * 128;
    const int col0 = blockIdx.x * 128;
    const uint32_t sb = smem_u32(smem);

    const int w = tid >> 5, lane = tid & 31;
    const int wm = w >> 2, wn = w & 3;      // 2 x 4 warp grid
    const int g = lane >> 2, t = lane & 3;

    float acc[4][4][4];
    #pragma unroll
    for (int i = 0; i < 4; i++)
        #pragma unroll
        for (int j = 0; j < 4; j++)
            #pragma unroll
            for (int e = 0; e < 4; e++) acc[i][j][e] = 0.f;

    const int r_ld = tid >> 2;   // 0..63
    const int c_ld = tid & 3;    // 0..3 (16B chunk within 64B row)
    const int nch  = K >> 5;

    auto load_stage = [&](int st, int k0) {
        uint32_t d0 = sb + st * STG;
        #pragma unroll
        for (int q = 0; q < 2; q++) {
            int r = r_ld + q * 64;
            uint32_t dof = (uint32_t)(r * 80 + c_ld * 16);
            size_t ga = (size_t)(row0 + r) * K + k0 + c_ld * 8;
            size_t gb = (size_t)(col0 + r) * K + k0 + c_ld * 8;
            cpa16(d0 + dof,         Ahi + ga);
            cpa16(d0 + 10240 + dof, Alo + ga);
            cpa16(d0 + 20480 + dof, Bhi + gb);
            cpa16(d0 + 30720 + dof, Blo + gb);
        }
    };

    load_stage(0, 0);
    CP_COMMIT();

    for (int ch = 0; ch < nch; ch++) {
        if (ch + 1 < nch) {
            load_stage((ch + 1) & 1, (ch + 1) << 5);
            CP_COMMIT();
            asm volatile("cp.async.wait_group 1;" ::: "memory");
        } else {
            asm volatile("cp.async.wait_group 0;" ::: "memory");
        }
        __syncthreads();

        const char* s0p = smem + (ch & 1) * STG;
        #pragma unroll
        for (int ks = 0; ks < 2; ks++) {
            uint32_t ah[4][4], al[4][4], bh[4][2], bl[4][2];
            #pragma unroll
            for (int mt = 0; mt < 4; mt++) {
                const char* ap = s0p + (wm * 64 + mt * 16 + g) * 80 + ks * 32 + t * 4;
                ah[mt][0] = *(const uint32_t*)(ap);
                ah[mt][1] = *(const uint32_t*)(ap + 640);
                ah[mt][2] = *(const uint32_t*)(ap + 16);
                ah[mt][3] = *(const uint32_t*)(ap + 656);
                al[mt][0] = *(const uint32_t*)(ap + 10240);
                al[mt][1] = *(const uint32_t*)(ap + 10880);
                al[mt][2] = *(const uint32_t*)(ap + 10256);
                al[mt][3] = *(const uint32_t*)(ap + 10896);
            }
            #pragma unroll
            for (int nt = 0; nt < 4; nt++) {
                const char* bp = s0p + 20480 + (wn * 32 + nt * 8 + g) * 80 + ks * 32 + t * 4;
                bh[nt][0] = *(const uint32_t*)(bp);
                bh[nt][1] = *(const uint32_t*)(bp + 16);
                bl[nt][0] = *(const uint32_t*)(bp + 10240);
                bl[nt][1] = *(const uint32_t*)(bp + 10256);
            }
            #pragma unroll
            for (int mt = 0; mt < 4; mt++)
                #pragma unroll
                for (int nt = 0; nt < 4; nt++)
                    mma_bf16(acc[mt][nt], ah[mt], bh[nt]);
            #pragma unroll
            for (int mt = 0; mt < 4; mt++)
                #pragma unroll
                for (int nt = 0; nt < 4; nt++)
                    mma_bf16(acc[mt][nt], ah[mt], bl[nt]);
            #pragma unroll
            for (int mt = 0; mt < 4; mt++)
                #pragma unroll
                for (int nt = 0; nt < 4; nt++)
                    mma_bf16(acc[mt][nt], al[mt], bh[nt]);
        }
        __syncthreads();
    }

    // epilogue: acc element map: a0=(row,col) a1=(row,col+1) a2=(row+8,col) a3=(row+8,col+1)
    #pragma unroll
    for (int mt = 0; mt < 4; mt++) {
        const int row = row0 + wm * 64 + mt * 16 + g;
        #pragma unroll
        for (int nt = 0; nt < 4; nt++) {
            const int col = col0 + wn * 32 + nt * 8 + 2 * t;
            const float* a = acc[mt][nt];
            const float b0v = bias ? bias[col]     : 0.f;
            const float b1v = bias ? bias[col + 1] : 0.f;
            const float v0 = a[0] + b0v, v1 = a[1] + b1v;
            const float v2 = a[2] + b0v, v3 = a[3] + b1v;
            if (EPI == 0) {
                *(float2*)(C + (size_t)row * N + col)       = make_float2(v0, v1);
                *(float2*)(C + (size_t)(row + 8) * N + col) = make_float2(v2, v3);
            } else if (EPI == 1) {
                float g0 = gelu_t(v0), g1 = gelu_t(v1), g2 = gelu_t(v2), g3 = gelu_t(v3);
                __nv_bfloat16 h0 = __float2bfloat16(g0), h1 = __float2bfloat16(g1);
                __nv_bfloat16 h2 = __float2bfloat16(g2), h3 = __float2bfloat16(g3);
                *(__nv_bfloat162*)(Chi + (size_t)row * N + col)       = __nv_bfloat162(h0, h1);
                *(__nv_bfloat162*)(Chi + (size_t)(row + 8) * N + col) = __nv_bfloat162(h2, h3);
                *(__nv_bfloat162*)(Clo + (size_t)row * N + col) =
                    __nv_bfloat162(__float2bfloat16(g0 - __bfloat162float(h0)),
                                   __float2bfloat16(g1 - __bfloat162float(h1)));
                *(__nv_bfloat162*)(Clo + (size_t)(row + 8) * N + col) =
                    __nv_bfloat162(__float2bfloat16(g2 - __bfloat162float(h2)),
                                   __float2bfloat16(g3 - __bfloat162float(h3)));
            } else {
                const int bb = row >> 8;   // row / Tc (rows 0..127 of block share batch)
                const float* gm = gmod + (size_t)bb * gstride;
                float2 x0 = *(float2*)(X + (size_t)row * N + col);
                float2 x1 = *(float2*)(X + (size_t)(row + 8) * N + col);
                x0.x += gm[col] * v0;     x0.y += gm[col + 1] * v1;
                x1.x += gm[col] * v2;     x1.y += gm[col + 1] * v3;
                *(float2*)(X + (size_t)row * N + col)       = x0;
                *(float2*)(X + (size_t)(row + 8) * N + col) = x1;
            }
        }
    }
}

// ---------------- weight prep: transpose [K,N] f32 -> [N,K] bf16 hi/lo ----------------
__global__ void wprep(const float* __restrict__ W, __nv_bfloat16* __restrict__ Whi,
                      __nv_bfloat16* __restrict__ Wlo, int K, int N) {
    __shared__ float t[32][33];
    int k0 = blockIdx.x * 32, n0 = blockIdx.y * 32;
    int tx = threadIdx.x, ty = threadIdx.y;   // 32 x 8
    #pragma unroll
    for (int i = 0; i < 4; i++)
        t[ty + i * 8][tx] = W[(size_t)(k0 + ty + i * 8) * N + n0 + tx];
    __syncthreads();
    #pragma unroll
    for (int i = 0; i < 4; i++) {
        float v = t[tx][ty + i * 8];
        int n = n0 + ty + i * 8, k = k0 + tx;
        __nv_bfloat16 h = __float2bfloat16(v);
        Whi[(size_t)n * K + k] = h;
        Wlo[(size_t)n * K + k] = __float2bfloat16(v - __bfloat162float(h));
    }
}

__global__ void split_kernel(const float* __restrict__ s, __nv_bfloat16* __restrict__ hi,
                             __nv_bfloat16* __restrict__ lo, int n) {
    int i = blockIdx.x * blockDim.x + threadIdx.x;
    if (i < n) {
        float v = s[i];
        __nv_bfloat16 h = __float2bfloat16(v);
        hi[i] = h;
        lo[i] = __float2bfloat16(v - __bfloat162float(h));
    }
}

// ---------------- elementwise kernels ----------------
__global__ void copy_kernel(const float* __restrict__ src, float* __restrict__ dst, int n) {
    int i = blockIdx.x * blockDim.x + threadIdx.x;
    if (i < n) dst[i] = src[i];
}
__global__ void silu_kernel(const float* __restrict__ c, float* __restrict__ out, int n) {
    int i = blockIdx.x * blockDim.x + threadIdx.x;
    if (i < n) { float x = c[i]; out[i] = x / (1.f + expf(-x)); }
}

__device__ __forceinline__ float block_reduce_sum(float v, float* red) {
    int tid = threadIdx.x;
    red[tid] = v;
    __syncthreads();
    #pragma unroll
    for (int s = 128; s > 0; s >>= 1) {
        if (tid < s) red[tid] += red[tid + s];
        __syncthreads();
    }
    float r = red[0];
    __syncthreads();
    return r;
}

// h = ln(x)*(1+ada[sc]) + ada[sh]  -> bf16 hi/lo split
__global__ void ln_mod_split(const float* __restrict__ x, const float* __restrict__ ada,
                             int off_shift, int off_scale,
                             __nv_bfloat16* __restrict__ hi, __nv_bfloat16* __restrict__ lo) {
    __shared__ float red[256];
    int row = blockIdx.x;
    int b   = row / Tc;
    int tid = threadIdx.x;
    const float* xr = x + (size_t)row * Dc;
    float v[4], s = 0.f;
    #pragma unroll
    for (int i = 0; i < 4; i++) { v[i] = xr[tid + i * 256]; s += v[i]; }
    float mean = block_reduce_sum(s, red) * (1.f / (float)Dc);
    float sq = 0.f;
    #pragma unroll
    for (int i = 0; i < 4; i++) { float d = v[i] - mean; sq += d * d; }
    float var = block_reduce_sum(sq, red) * (1.f / (float)Dc);
    float rstd = rsqrtf(var + 1e-5f);
    const float* ab = ada + (size_t)b * 6 * Dc;
    #pragma unroll
    for (int i = 0; i < 4; i++) {
        int d = tid + i * 256;
        float a = (v[i] - mean) * rstd;
        float o = a * (1.f + ab[off_scale + d]) + ab[off_shift + d];
        __nv_bfloat16 h = __float2bfloat16(o);
        hi[(size_t)row * Dc + d] = h;
        lo[(size_t)row * Dc + d] = __float2bfloat16(o - __bfloat162float(h));
    }
}

// per-head RMSNorm + RoPE (+ uniform multiplier), in-place fp32
__global__ void rmsrope_kernel(float* __restrict__ t, const float* __restrict__ w,
                               int S, float cmul, const float* __restrict__ gate) {
    int warp = (blockIdx.x * blockDim.x + threadIdx.x) >> 5;
    int lane = threadIdx.x & 31;
    int row  = warp;
    int s    = (row / Hc) % S;
    float* p = t + (size_t)row * HDc;
    float x0 = p[lane], x1 = p[lane + 32];
    float ss = x0 * x0 + x1 * x1;
    #pragma unroll
    for (int o = 16; o; o >>= 1) ss += __shfl_xor_sync(0xffffffffu, ss, o);
    float inv = rsqrtf(ss * (1.f / (float)HDc) + 1e-6f);
    x0 = x0 * inv * w[lane];
    x1 = x1 * inv * w[lane + 32];
    float fr = (float)s * expf(-(float)lane * 0.28782313662425575f);
    float c  = cosf(fr), sn = sinf(fr);
    float mult = cmul;
    if (gate) mult *= 1.f / (1.f + expf(-gate[0]));
    p[lane]      = (x0 * c - x1 * sn) * mult;
    p[lane + 32] = (x1 * c + x0 * sn) * mult;
}

// ada: C[b,n] = silu(cond)[b,:] @ Wada[:,n] + bias
__global__ void small_gemm_kernel(const float* __restrict__ A, const float* __restrict__ W,
                                  const float* __restrict__ bias, float* __restrict__ C,
                                  int Nn, int Kk) {
    int n = blockIdx.x * blockDim.x + threadIdx.x;
    int b = blockIdx.y;
    if (n >= Nn) return;
    const float* a = A + (size_t)b * Kk;
    float acc = 0.f;
    #pragma unroll 4
    for (int k = 0; k < Kk; k++) acc += a[k] * W[(size_t)k * Nn + n];
    C[(size_t)b * Nn + n] = acc + (bias ? bias[n] : 0.f);
}

// ---------------- flash attention (fp32) over 3 KV segments, output bf16 split ----------------
__global__ __launch_bounds__(128) void flash_kernel(
    const float* __restrict__ q,
    const float* __restrict__ ks, const float* __restrict__ vs,
    const float* __restrict__ ka, const float* __restrict__ va,
    const float* __restrict__ kt, const float* __restrict__ vt,
    __nv_bfloat16* __restrict__ ohi, __nv_bfloat16* __restrict__ olo)
{
    __shared__ float4 Ks4[32][16];
    __shared__ float4 Vs4[32][16];
    int tid = threadIdx.x;
    int bh  = blockIdx.y;
    int b   = bh / Hc, h = bh % Hc;
    int qi  = blockIdx.x * 128 + tid;

    float qr[64], oa[64];
    const float* qp = q + (size_t)(b * Tc + qi) * Dc + h * HDc;
    #pragma unroll
    for (int j = 0; j < 16; j++) {
        float4 v4 = *(const float4*)&qp[j * 4];
        qr[4*j] = v4.x; qr[4*j+1] = v4.y; qr[4*j+2] = v4.z; qr[4*j+3] = v4.w;
    }
    #pragma unroll
    for (int d = 0; d < 64; d++) oa[d] = 0.f;
    float m = -1e30f, l = 0.f;

    const float* Kseg[3] = {ks, ka, kt};
    const float* Vseg[3] = {vs, va, vt};
    const int    Slen[3] = {Tc, SAc, STc};

    #pragma unroll
    for (int seg = 0; seg < 3; seg++) {
        const float* K = Kseg[seg];
        const float* V = Vseg[seg];
        int S = Slen[seg];
        for (int s0 = 0; s0 < S; s0 += 32) {
            __syncthreads();
            #pragma unroll
            for (int i = 0; i < 4; i++) {
                int idx = tid + i * 128;
                int r = idx >> 4, cc = idx & 15;
                size_t base = (size_t)(b * S + s0 + r) * Dc + h * HDc + cc * 4;
                Ks4[r][cc] = *(const float4*)&K[base];
                Vs4[r][cc] = *(const float4*)&V[base];
            }
            __syncthreads();
            float sc[32];
            float tmax = -1e30f;
            #pragma unroll
            for (int s = 0; s < 32; s++) {
                float d0 = 0.f, d1 = 0.f, d2 = 0.f, d3 = 0.f;
                #pragma unroll
                for (int j = 0; j < 16; j++) {
                    float4 kv = Ks4[s][j];
                    d0 = fmaf(qr[4*j],   kv.x, d0);
                    d1 = fmaf(qr[4*j+1], kv.y, d1);
                    d2 = fmaf(qr[4*j+2], kv.z, d2);
                    d3 = fmaf(qr[4*j+3], kv.w, d3);
                }
                float d = (d0 + d1) + (d2 + d3);
                sc[s] = d;
                tmax = fmaxf(tmax, d);
            }
            float mnew = fmaxf(m, tmax);
            float corr = __expf(m - mnew);
            l *= corr;
            #pragma unroll
            for (int d = 0; d < 64; d++) oa[d] *= corr;
            #pragma unroll
            for (int s = 0; s < 32; s++) {
                float p = __expf(sc[s] - mnew);
                l += p;
                #pragma unroll
                for (int j = 0; j < 16; j++) {
                    float4 vv = Vs4[s][j];
                    oa[4*j]   = fmaf(p, vv.x, oa[4*j]);
                    oa[4*j+1] = fmaf(p, vv.y, oa[4*j+1]);
                    oa[4*j+2] = fmaf(p, vv.z, oa[4*j+2]);
                    oa[4*j+3] = fmaf(p, vv.w, oa[4*j+3]);
                }
            }
            m = mnew;
        }
    }
    float invl = 1.f / l;
    size_t ob = (size_t)(b * Tc + qi) * Dc + h * HDc;
    #pragma unroll
    for (int d = 0; d < 64; d++) {
        float v = oa[d] * invl;
        __nv_bfloat16 hb = __float2bfloat16(v);
        ohi[ob + d] = hb;
        olo[ob + d] = __float2bfloat16(v - __bfloat162float(hb));
    }
}

// ---------------- final LN + tiny projection ----------------
__global__ void final_kernel(const float* __restrict__ x, const float* __restrict__ lw,
                             const float* __restrict__ lb, const float* __restrict__ Wout,
                             const float* __restrict__ bout, float* __restrict__ out) {
    __shared__ float red[256];
    int row = blockIdx.x;
    int tid = threadIdx.x;
    const float* xr = x + (size_t)row * Dc;
    float v[4], s = 0.f;
    #pragma unroll
    for (int i = 0; i < 4; i++) { v[i] = xr[tid + i * 256]; s += v[i]; }
    float mean = block_reduce_sum(s, red) * (1.f / (float)Dc);
    float sq = 0.f;
    #pragma unroll
    for (int i = 0; i < 4; i++) { float d = v[i] - mean; sq += d * d; }
    float var = block_reduce_sum(sq, red) * (1.f / (float)Dc);
    float rstd = rsqrtf(var + 1e-5f);
    float p0 = 0.f, p1 = 0.f, p2 = 0.f;
    #pragma unroll
    for (int i = 0; i < 4; i++) {
        int d = tid + i * 256;
        float y = (v[i] - mean) * rstd * lw[d] + lb[d];
        p0 = fmaf(y, Wout[d * OUTc + 0], p0);
        p1 = fmaf(y, Wout[d * OUTc + 1], p1);
        p2 = fmaf(y, Wout[d * OUTc + 2], p2);
    }
    p0 = block_reduce_sum(p0, red);
    p1 = block_reduce_sum(p1, red);
    p2 = block_reduce_sum(p2, red);
    if (tid == 0) {
        out[row * OUTc + 0] = p0 + bout[0];
        out[row * OUTc + 1] = p1 + bout[1];
        out[row * OUTc + 2] = p2 + bout[2];
    }
}

// ---------------- launch ----------------
extern "C" void kernel_launch(void* const* d_in, const int* in_sizes, int n_in,
                              void* d_out, int out_size)
{
    (void)in_sizes; (void)n_in; (void)out_size;
    const float* x    = (const float*)d_in[0];
    const float* cond = (const float*)d_in[1];
    const float* adp  = (const float*)d_in[2];
    const float* task = (const float*)d_in[3];
    const float* Wq   = (const float*)d_in[4];
    const float* bq   = (const float*)d_in[5];
    const float* Wks  = (const float*)d_in[6];
    const float* Wvs  = (const float*)d_in[7];
    const float* Wka  = (const float*)d_in[8];
    const float* Wva  = (const float*)d_in[9];
    const float* Wkt  = (const float*)d_in[10];
    const float* Wvt  = (const float*)d_in[11];
    const float* Wo   = (const float*)d_in[12];
    const float* bo   = (const float*)d_in[13];
    const float* qnw  = (const float*)d_in[14];
    const float* knw  = (const float*)d_in[15];
    const float* gate = (const float*)d_in[16];
    const float* Wada = (const float*)d_in[17];
    const float* bada = (const float*)d_in[18];
    const float* W1   = (const float*)d_in[19];
    const float* b1   = (const float*)d_in[20];
    const float* W2   = (const float*)d_in[21];
    const float* b2   = (const float*)d_in[22];
    const float* lnfw = (const float*)d_in[23];
    const float* lnfb = (const float*)d_in[24];
    const float* Wout = (const float*)d_in[25];
    const float* bout = (const float*)d_in[26];
    float* out = (float*)d_out;

    cudaFuncSetAttribute(mma_gemm<0>, cudaFuncAttributeMaxDynamicSharedMemorySize, GSMEM);
    cudaFuncSetAttribute(mma_gemm<1>, cudaFuncAttributeMaxDynamicSharedMemorySize, GSMEM);
    cudaFuncSetAttribute(mma_gemm<2>, cudaFuncAttributeMaxDynamicSharedMemorySize, GSMEM);

    float *px, *pq, *pks, *pvs, *pka, *pva, *pkt, *pvt, *pada, *psc;
    __nv_bfloat16 *phh, *phl, *poh, *pol, *pfh, *pfl, *pah, *pal, *pth, *ptl, *pwh, *pwl;
    cudaGetSymbolAddress((void**)&px,  g_x);
    cudaGetSymbolAddress((void**)&pq,  g_q);
    cudaGetSymbolAddress((void**)&pks, g_ks);
    cudaGetSymbolAddress((void**)&pvs, g_vs);
    cudaGetSymbolAddress((void**)&pka, g_ka);
    cudaGetSymbolAddress((void**)&pva, g_va);
    cudaGetSymbolAddress((void**)&pkt, g_kt);
    cudaGetSymbolAddress((void**)&pvt, g_vt);
    cudaGetSymbolAddress((void**)&pada, g_ada);
    cudaGetSymbolAddress((void**)&psc,  g_sc);
    cudaGetSymbolAddress((void**)&phh, g_h_hi);  cudaGetSymbolAddress((void**)&phl, g_h_lo);
    cudaGetSymbolAddress((void**)&poh, g_o_hi);  cudaGetSymbolAddress((void**)&pol, g_o_lo);
    cudaGetSymbolAddress((void**)&pfh, g_ff_hi); cudaGetSymbolAddress((void**)&pfl, g_ff_lo);
    cudaGetSymbolAddress((void**)&pah, g_adp_hi); cudaGetSymbolAddress((void**)&pal, g_adp_lo);
    cudaGetSymbolAddress((void**)&pth, g_tsk_hi); cudaGetSymbolAddress((void**)&ptl, g_tsk_lo);
    cudaGetSymbolAddress((void**)&pwh, g_w_hi);  cudaGetSymbolAddress((void**)&pwl, g_w_lo);

    // per-call prep: x copy, silu(cond), adp/task split, weight transpose+split
    copy_kernel<<<(MTc*Dc)/256, 256>>>(x, px, MTc*Dc);
    silu_kernel<<<(Bc*Dc)/256, 256>>>(cond, psc, Bc*Dc);
    split_kernel<<<(MAc*Dc)/256, 256>>>(adp,  pah, pal, MAc*Dc);
    split_kernel<<<(MSc*Dc)/256, 256>>>(task, pth, ptl, MSc*Dc);

    const float* wsrc[8] = {Wq, Wks, Wvs, Wka, Wva, Wkt, Wvt, Wo};
    for (int i = 0; i < Lc; i++) {
        size_t base = (size_t)i * WPLc;
        for (int mtx = 0; mtx < 8; mtx++) {
            wprep<<<dim3(Dc/32, Dc/32), dim3(32, 8)>>>(
                wsrc[mtx] + (size_t)i * DDc, pwh + base + (size_t)mtx * DDc,
                pwl + base + (size_t)mtx * DDc, Dc, Dc);
        }
        wprep<<<dim3(Dc/32, DFFc/32), dim3(32, 8)>>>(
            W1 + (size_t)i * Dc * DFFc, pwh + base + 8*DDc, pwl + base + 8*DDc, Dc, DFFc);
        wprep<<<dim3(DFFc/32, Dc/32), dim3(32, 8)>>>(
            W2 + (size_t)i * DFFc * Dc, pwh + base + 8*DDc + (size_t)Dc*DFFc,
            pwl + base + 8*DDc + (size_t)Dc*DFFc, DFFc, Dc);
    }

    for (int i = 0; i < Lc; i++) {
        size_t wb = (size_t)i * WPLc;
        __nv_bfloat16* wq  = pwh + wb + 0*(size_t)DDc; __nv_bfloat16* wql = pwl + wb + 0*(size_t)DDc;
        __nv_bfloat16* wks = pwh + wb + 1*(size_t)DDc; __nv_bfloat16* wksl= pwl + wb + 1*(size_t)DDc;
        __nv_bfloat16* wvs = pwh + wb + 2*(size_t)DDc; __nv_bfloat16* wvsl= pwl + wb + 2*(size_t)DDc;
        __nv_bfloat16* wka = pwh + wb + 3*(size_t)DDc; __nv_bfloat16* wkal= pwl + wb + 3*(size_t)DDc;
        __nv_bfloat16* wva = pwh + wb + 4*(size_t)DDc; __nv_bfloat16* wval= pwl + wb + 4*(size_t)DDc;
        __nv_bfloat16* wkt = pwh + wb + 5*(size_t)DDc; __nv_bfloat16* wktl= pwl + wb + 5*(size_t)DDc;
        __nv_bfloat16* wvt = pwh + wb + 6*(size_t)DDc; __nv_bfloat16* wvtl= pwl + wb + 6*(size_t)DDc;
        __nv_bfloat16* wo  = pwh + wb + 7*(size_t)DDc; __nv_bfloat16* wol = pwl + wb + 7*(size_t)DDc;
        __nv_bfloat16* w1  = pwh + wb + 8*(size_t)DDc; __nv_bfloat16* w1l = pwl + wb + 8*(size_t)DDc;
        __nv_bfloat16* w2  = pwh + wb + 8*(size_t)DDc + (size_t)Dc*DFFc;
        __nv_bfloat16* w2l = pwl + wb + 8*(size_t)DDc + (size_t)Dc*DFFc;

        small_gemm_kernel<<<dim3((6*Dc)/256, Bc), 256>>>(
            psc, Wada + (size_t)i*Dc*6*Dc, bada + (size_t)i*6*Dc, pada, 6*Dc, Dc);

        ln_mod_split<<<MTc, 256>>>(px, pada, 0, Dc, phh, phl);

        mma_gemm<0><<<dim3(Dc/128, MTc/128), 256, GSMEM>>>(phh, phl, wq,  wql,  bq + (size_t)i*Dc, pq,  MTc, Dc, Dc, nullptr, 0, nullptr, nullptr, nullptr);
        mma_gemm<0><<<dim3(Dc/128, MTc/128), 256, GSMEM>>>(phh, phl, wks, wksl, nullptr,           pks, MTc, Dc, Dc, nullptr, 0, nullptr, nullptr, nullptr);
        mma_gemm<0><<<dim3(Dc/128, MTc/128), 256, GSMEM>>>(phh, phl, wvs, wvsl, nullptr,           pvs, MTc, Dc, Dc, nullptr, 0, nullptr, nullptr, nullptr);
        mma_gemm<0><<<dim3(Dc/128, MAc/128), 256, GSMEM>>>(pah, pal, wka, wkal, nullptr,           pka, MAc, Dc, Dc, nullptr, 0, nullptr, nullptr, nullptr);
        mma_gemm<0><<<dim3(Dc/128, MAc/128), 256, GSMEM>>>(pah, pal, wva, wval, nullptr,           pva, MAc, Dc, Dc, nullptr, 0, nullptr, nullptr, nullptr);
        mma_gemm<0><<<dim3(Dc/128, MSc/128), 256, GSMEM>>>(pth, ptl, wkt, wktl, nullptr,           pkt, MSc, Dc, Dc, nullptr, 0, nullptr, nullptr, nullptr);
        mma_gemm<0><<<dim3(Dc/128, MSc/128), 256, GSMEM>>>(pth, ptl, wvt, wvtl, nullptr,           pvt, MSc, Dc, Dc, nullptr, 0, nullptr, nullptr, nullptr);

        rmsrope_kernel<<<(MTc*Hc*32)/256, 256>>>(pq,  qnw + (size_t)i*HDc, Tc,  0.125f, nullptr);
        rmsrope_kernel<<<(MTc*Hc*32)/256, 256>>>(pks, knw + (size_t)i*HDc, Tc,  1.f,    nullptr);
        rmsrope_kernel<<<(MAc*Hc*32)/256, 256>>>(pka, knw + (size_t)i*HDc, SAc, 1.f,    nullptr);
        rmsrope_kernel<<<(MSc*Hc*32)/256, 256>>>(pkt, knw + (size_t)i*HDc, STc, 1.f,    gate + i);

        flash_kernel<<<dim3(Tc/128, Bc*Hc), 128>>>(pq, pks, pvs, pka, pva, pkt, pvt, poh, pol);

        mma_gemm<2><<<dim3(Dc/128, MTc/128), 256, GSMEM>>>(poh, pol, wo, wol, bo + (size_t)i*Dc, nullptr,
                                                           MTc, Dc, Dc, pada + 2*Dc, 6*Dc, px, nullptr, nullptr);

        ln_mod_split<<<MTc, 256>>>(px, pada, 3*Dc, 4*Dc, phh, phl);

        mma_gemm<1><<<dim3(DFFc/128, MTc/128), 256, GSMEM>>>(phh, phl, w1, w1l, b1 + (size_t)i*DFFc, nullptr,
                                                             MTc, DFFc, Dc, nullptr, 0, nullptr, pfh, pfl);

        mma_gemm<2><<<dim3(Dc/128, MTc/128), 256, GSMEM>>>(pfh, pfl, w2, w2l, b2 + (size_t)i*Dc, nullptr,
                                                           MTc, Dc, DFFc, pada + 5*Dc, 6*Dc, px, nullptr, nullptr);
    }

    final_kernel<<<MTc, 256>>>(px, lnfw, lnfb, Wout, bout, out);
}